// round 16
// baseline (speedup 1.0000x reference)
#include <cuda_runtime.h>
#include <cuda_fp16.h>
#include <cstdint>

#define N_NODES 100000
#define N_EDGES 600000
#define CH 128
#define NPB 64            // nodes per block tile (tail block handles 32)
#define NBLK 1563         // ceil(100000/64)
#define NCHUNK 98         // ceil(100000/1024)
#define AS_H2 68          // half2 per row: 64 + 4 pad -> conflict-free fragment LDS
#define PREP_BLOCKS 16    // 4096 uint4 / 256
#define XPAD_BLOCKS 391   // ceil(100000/256)
// zeroed region: [0,N) deg | [N, N+2*NCHUNK) lookback u64 | then 4*N floats agg
#define ZBASE_AGG (N_NODES + 2 * NCHUNK)            // 100196 ints, 16B aligned (x4)
#define ZCOUNT (ZBASE_AGG + 4 * N_NODES)

// ---------------- scratch (static device globals; no allocation) ----------------
__device__ __align__(16) int g_zeroed[ZCOUNT];
__device__ float  g_deginv[N_NODES];
__device__ int    g_off[N_NODES + 1];
__device__ int    g_cur[N_NODES];
__device__ int    g_col[N_EDGES];
__device__ __align__(16) float4 g_x4[N_NODES];   // x padded to 16B rows
__device__ __align__(16) __half g_h1[(size_t)N_NODES * CH];
__device__ __align__(16) __half g_h2[(size_t)N_NODES * CH];
// fp16 fragment-ordered weights: uint4 idx = ((((wn*2+pass)*8 + kt)*2 + g)*32 + lane)
__device__ __align__(16) __half g_Wt2[128 * 256];
__device__ __align__(16) __half g_Wt3[128 * 256];

// ---------------- helpers ----------------
__device__ __forceinline__ int warp_incl_scan(int v, int lane) {
    #pragma unroll
    for (int o = 1; o < 32; o <<= 1) {
        int t = __shfl_up_sync(0xffffffffu, v, o);
        if (lane >= o) v += t;
    }
    return v;
}
__device__ __forceinline__ void mma_f16(float* c, const unsigned* a, const unsigned* b) {
    asm volatile(
        "mma.sync.aligned.m16n8k16.row.col.f32.f16.f16.f32 "
        "{%0,%1,%2,%3}, {%4,%5,%6,%7}, {%8,%9}, {%0,%1,%2,%3};"
        : "+f"(c[0]), "+f"(c[1]), "+f"(c[2]), "+f"(c[3])
        : "r"(a[0]), "r"(a[1]), "r"(a[2]), "r"(a[3]), "r"(b[0]), "r"(b[1]));
}
__device__ __forceinline__ unsigned h2u(__half2 h) {
    return *reinterpret_cast<unsigned*>(&h);
}
__device__ __forceinline__ void acc4_h2(float4& A, uint2 v) {
    float2 lo = __half22float2(*reinterpret_cast<__half2*>(&v.x));
    float2 hi = __half22float2(*reinterpret_cast<__half2*>(&v.y));
    A.x += lo.x; A.y += lo.y; A.z += hi.x; A.w += hi.y;
}

// ---------------- fused prep (16) + x-pad (391) + edge hist/agg (rest) ----------------
__global__ void histprep_kernel(const int* __restrict__ src,
                                const int* __restrict__ dst,
                                const float* __restrict__ x,
                                const float* __restrict__ W2l, const float* __restrict__ W2r,
                                const float* __restrict__ W3l, const float* __restrict__ W3r) {
    if (blockIdx.x < PREP_BLOCKS) {
        int p = blockIdx.x * blockDim.x + threadIdx.x;   // 4096 uint4
        if (p >= 4096) return;
        int lane = p & 31;
        int g    = (p >> 5) & 1;
        int kt   = (p >> 6) & 7;
        int pass = (p >> 9) & 1;
        int wn   = (p >> 10) & 3;
        int gid = lane >> 2, tig = lane & 3;
        int k0 = kt * 16 + tig * 2;

        const float* Wa2 = pass ? W2r : W2l;
        const float* Wa3 = pass ? W3r : W3l;

        unsigned out2[4], out3[4];
        #pragma unroll
        for (int j = 0; j < 2; j++) {
            int n = wn * 32 + (g * 2 + j) * 8 + gid;
            out2[j * 2 + 0] = h2u(__floats2half2_rn(Wa2[(k0 + 0) * CH + n], Wa2[(k0 + 1) * CH + n]));
            out2[j * 2 + 1] = h2u(__floats2half2_rn(Wa2[(k0 + 8) * CH + n], Wa2[(k0 + 9) * CH + n]));
            out3[j * 2 + 0] = h2u(__floats2half2_rn(Wa3[(k0 + 0) * CH + n], Wa3[(k0 + 1) * CH + n]));
            out3[j * 2 + 1] = h2u(__floats2half2_rn(Wa3[(k0 + 8) * CH + n], Wa3[(k0 + 9) * CH + n]));
        }
        ((uint4*)g_Wt2)[p] = make_uint4(out2[0], out2[1], out2[2], out2[3]);
        ((uint4*)g_Wt3)[p] = make_uint4(out3[0], out3[1], out3[2], out3[3]);
    } else if (blockIdx.x < PREP_BLOCKS + XPAD_BLOCKS) {
        int i = (blockIdx.x - PREP_BLOCKS) * blockDim.x + threadIdx.x;
        if (i < N_NODES)
            g_x4[i] = make_float4(x[i * 3 + 0], x[i * 3 + 1], x[i * 3 + 2], 0.0f);
    } else {
        int i = (blockIdx.x - PREP_BLOCKS - XPAD_BLOCKS) * blockDim.x + threadIdx.x;
        if (i < N_EDGES) {
            int d = dst[i];
            int s = src[i];
            atomicAdd(&g_zeroed[d], 1);
            float* agg = (float*)(g_zeroed + ZBASE_AGG) + (size_t)d * 4;
            atomicAdd(&agg[0], x[s * 3 + 0]);
            atomicAdd(&agg[1], x[s * 3 + 1]);
            atomicAdd(&agg[2], x[s * 3 + 2]);
        }
    }
}

// ---------------- single-pass decoupled-lookback scan ----------------
__global__ void __launch_bounds__(1024, 1)
scanlb_kernel() {
    __shared__ int wsum[32];
    __shared__ int sh_excl;
    volatile unsigned long long* look =
        (volatile unsigned long long*)(g_zeroed + N_NODES);

    int b = blockIdx.x, tid = threadIdx.x;
    int wid = tid >> 5, lane = tid & 31;
    int i = b * 1024 + tid;
    int v = (i < N_NODES) ? g_zeroed[i] : 0;

    int incl = warp_incl_scan(v, lane);
    if (lane == 31) wsum[wid] = incl;
    __syncthreads();

    if (wid == 0) {
        int ws = wsum[lane];
        int wi = warp_incl_scan(ws, lane);
        wsum[lane] = wi - ws;                     // exclusive warp prefix
        int tot = __shfl_sync(0xffffffffu, wi, 31);

        if (lane == 0)
            look[b] = ((unsigned long long)(b == 0 ? 2u : 1u) << 32) | (unsigned)tot;

        int excl = 0;
        if (b > 0) {
            int win = b - 1;
            while (true) {
                int j = win - lane;
                unsigned long long s = 0;
                if (j >= 0) {
                    do { s = look[j]; } while ((unsigned)(s >> 32) == 0u);
                }
                unsigned flag = (j >= 0) ? (unsigned)(s >> 32) : 0u;
                int val = (int)(unsigned)s;
                unsigned mask = __ballot_sync(0xffffffffu, flag == 2u);
                int contrib;
                if (mask) {
                    int lz = __ffs(mask) - 1;
                    contrib = (lane <= lz && j >= 0) ? val : 0;
                } else {
                    contrib = (j >= 0) ? val : 0;
                }
                #pragma unroll
                for (int o = 16; o > 0; o >>= 1)
                    contrib += __shfl_xor_sync(0xffffffffu, contrib, o);
                excl += contrib;
                if (mask) break;
                win -= 32;
            }
            if (lane == 0)
                look[b] = (2ULL << 32) | (unsigned)(excl + tot);
        }
        if (lane == 0) sh_excl = excl;
    }
    __syncthreads();

    int inclusive = sh_excl + wsum[wid] + incl;
    if (i < N_NODES) {
        g_off[i + 1]  = inclusive;
        g_cur[i]      = inclusive - v;
        g_deginv[i]   = (v > 0) ? (1.0f / (float)v) : 0.0f;
        if (i == 0) g_off[0] = 0;
    }
}

__global__ void fill_kernel(const int* __restrict__ src, const int* __restrict__ dst) {
    int i = blockIdx.x * blockDim.x + threadIdx.x;
    if (i < N_EDGES) {
        int d   = dst[i];
        int pos = atomicAdd(&g_cur[d], 1);
        g_col[pos] = src[i];
    }
}

// ---------------- layer 1 (K = 3): DENSE — agg pre-summed by atomics ----------------
// block = 128 nodes, 256 threads. No CSR dependency.
__global__ void __launch_bounds__(256)
layer1_kernel(const float* __restrict__ Wl,
              const float* __restrict__ Wr,
              const float* __restrict__ b,
              __half* __restrict__ hout) {
    __shared__ __align__(16) float tile[128][8];   // [agg(4) | own(4)]
    int tid  = threadIdx.x;
    int base = blockIdx.x * 128;

    if (tid < 128) {
        int node = base + tid;
        if (node < N_NODES) {
            int deg = g_zeroed[node];
            float di = (deg > 0) ? (1.0f / (float)deg) : 0.0f;
            const float4* aggp = (const float4*)(g_zeroed + ZBASE_AGG);
            float4 ag = aggp[node];
            *(float4*)&tile[tid][0] = make_float4(ag.x * di, ag.y * di, ag.z * di, 0.0f);
            *(float4*)&tile[tid][4] = g_x4[node];
        }
    }
    __syncthreads();

    // epilogue: col pair = tid&63, node group = tid>>6 (4 groups of 32 nodes)
    int c2  = tid & 63;
    int g2  = tid >> 6;
    int col = c2 * 2;
    float wl0a = Wl[0 * CH + col],     wl1a = Wl[1 * CH + col],     wl2a = Wl[2 * CH + col];
    float wl0b = Wl[0 * CH + col + 1], wl1b = Wl[1 * CH + col + 1], wl2b = Wl[2 * CH + col + 1];
    float wr0a = Wr[0 * CH + col],     wr1a = Wr[1 * CH + col],     wr2a = Wr[2 * CH + col];
    float wr0b = Wr[0 * CH + col + 1], wr1b = Wr[1 * CH + col + 1], wr2b = Wr[2 * CH + col + 1];
    float bb0 = b[col], bb1 = b[col + 1];

    int nend = min(g2 * 32 + 32, N_NODES - base);
    for (int n = g2 * 32; n < nend; n++) {
        float4 ag = *(const float4*)&tile[n][0];
        float4 ow = *(const float4*)&tile[n][4];
        float acc0 = bb0 + ag.x * wl0a + ag.y * wl1a + ag.z * wl2a
                         + ow.x * wr0a + ow.y * wr1a + ow.z * wr2a;
        float acc1 = bb1 + ag.x * wl0b + ag.y * wl1b + ag.z * wl2b
                         + ow.x * wr0b + ow.y * wr1b + ow.z * wr2b;
        __half2 hv = __floats2half2_rn(fmaxf(acc0, 0.0f), fmaxf(acc1, 0.0f));
        *(__half2*)&hout[(size_t)(base + n) * CH + col] = hv;
    }
}

// ---------------- layers 2/3: dual-buffer single-sync fp16 TC GEMM ----------------
template <bool HALF_OUT>
__global__ void __launch_bounds__(256, 4)
layerTC_kernel(const __half* __restrict__ hin, void* __restrict__ hout_v,
               const __half* __restrict__ Wt, const float* __restrict__ bias) {
    __shared__ __align__(16) unsigned As[2][NPB * AS_H2];   // 34.8 KB

    int tid  = threadIdx.x;
    int warp = tid >> 5, lane = tid & 31;
    int base = blockIdx.x * NPB;

    int wm = warp >> 2;          // 0..1  -> M rows [wm*32, wm*32+32)
    int wn = warp & 3;           // 0..3  -> N cols [wn*32, wn*32+32)
    int gid = lane >> 2, tig = lane & 3;

    float acc[2][4][4];
    #pragma unroll
    for (int mt = 0; mt < 2; mt++)
        #pragma unroll
        for (int nt = 0; nt < 4; nt++)
            #pragma unroll
            for (int r = 0; r < 4; r++) acc[mt][nt][r] = 0.0f;

    const uint4* Wf = (const uint4*)Wt;

    // ---- Phase A: gather into As[0]; own rows into As[1]; one sync ----
    #pragma unroll
    for (int q = 0; q < 4; q++) {
        int nA = warp + q * 16;
        int nB = nA + 8;
        int nodeA = base + nA, nodeB = base + nB;
        bool okA = nodeA < N_NODES, okB = nodeB < N_NODES;
        int sA = okA ? g_off[nodeA] : 0, eA = okA ? g_off[nodeA + 1] : 0;
        int sB = okB ? g_off[nodeB] : 0, eB = okB ? g_off[nodeB + 1] : 0;
        int safeA = min(sA, N_EDGES - 1);
        int safeB = min(sB, N_EDGES - 1);
        int maxd = max(eA - sA, eB - sB);

        float4 A0 = make_float4(0.f, 0.f, 0.f, 0.f);
        float4 A1 = A0, B0 = A0, B1 = A0;

        for (int w = 0; w < maxd; w += 4) {
            int ja[4], jb[4];
            bool pa[4], pb[4];
            #pragma unroll
            for (int j = 0; j < 4; j++) {
                int ia = sA + w + j, ib = sB + w + j;
                pa[j] = ia < eA;  pb[j] = ib < eB;
                ja[j] = g_col[pa[j] ? ia : safeA];
                jb[j] = g_col[pb[j] ? ib : safeB];
            }
            uint2 va0 = *(const uint2*)&hin[(size_t)ja[0] * CH + lane * 4];
            uint2 va1 = *(const uint2*)&hin[(size_t)ja[1] * CH + lane * 4];
            uint2 va2 = *(const uint2*)&hin[(size_t)ja[2] * CH + lane * 4];
            uint2 va3 = *(const uint2*)&hin[(size_t)ja[3] * CH + lane * 4];
            uint2 vb0 = *(const uint2*)&hin[(size_t)jb[0] * CH + lane * 4];
            uint2 vb1 = *(const uint2*)&hin[(size_t)jb[1] * CH + lane * 4];
            uint2 vb2 = *(const uint2*)&hin[(size_t)jb[2] * CH + lane * 4];
            uint2 vb3 = *(const uint2*)&hin[(size_t)jb[3] * CH + lane * 4];
            if (pa[0]) acc4_h2(A0, va0);
            if (pa[1]) acc4_h2(A1, va1);
            if (pa[2]) acc4_h2(A0, va2);
            if (pa[3]) acc4_h2(A1, va3);
            if (pb[0]) acc4_h2(B0, vb0);
            if (pb[1]) acc4_h2(B1, vb1);
            if (pb[2]) acc4_h2(B0, vb2);
            if (pb[3]) acc4_h2(B1, vb3);
        }

        if (okA) {
            float di = g_deginv[nodeA];
            uint2 st;
            st.x = h2u(__floats2half2_rn((A0.x + A1.x) * di, (A0.y + A1.y) * di));
            st.y = h2u(__floats2half2_rn((A0.z + A1.z) * di, (A0.w + A1.w) * di));
            *(uint2*)&As[0][nA * AS_H2 + lane * 2] = st;
            uint2 own = *(const uint2*)&hin[(size_t)nodeA * CH + lane * 4];
            *(uint2*)&As[1][nA * AS_H2 + lane * 2] = own;
        }
        if (okB) {
            float di = g_deginv[nodeB];
            uint2 st;
            st.x = h2u(__floats2half2_rn((B0.x + B1.x) * di, (B0.y + B1.y) * di));
            st.y = h2u(__floats2half2_rn((B0.z + B1.z) * di, (B0.w + B1.w) * di));
            *(uint2*)&As[0][nB * AS_H2 + lane * 2] = st;
            uint2 own = *(const uint2*)&hin[(size_t)nodeB * CH + lane * 4];
            *(uint2*)&As[1][nB * AS_H2 + lane * 2] = own;
        }
    }
    __syncthreads();

    // ---- Phase B: both passes back-to-back ----
    #pragma unroll
    for (int pass = 0; pass < 2; pass++) {
        #pragma unroll
        for (int kt = 0; kt < 8; kt++) {
            unsigned i0 = ((((unsigned)(wn * 2 + pass) * 8 + kt) * 2) * 32) + lane;
            uint4 q0 = Wf[i0];        // nt 0,1
            uint4 q1 = Wf[i0 + 32];   // nt 2,3
            unsigned bfr[4][2] = {
                { q0.x, q0.y }, { q0.z, q0.w },
                { q1.x, q1.y }, { q1.z, q1.w } };

            unsigned kc = kt * 8;     // half2 column base within row
            #pragma unroll
            for (int mt = 0; mt < 2; mt++) {
                unsigned r0 = (unsigned)(wm * 32 + mt * 16 + gid) * AS_H2 + kc + tig;
                unsigned a[4];
                a[0] = As[pass][r0];
                a[1] = As[pass][r0 + 8 * AS_H2];
                a[2] = As[pass][r0 + 4];
                a[3] = As[pass][r0 + 8 * AS_H2 + 4];
                #pragma unroll
                for (int nt = 0; nt < 4; nt++)
                    mma_f16(acc[mt][nt], a, bfr[nt]);
            }
        }
    }

    // ---- epilogue: bias + relu + store ----
    #pragma unroll
    for (int nt = 0; nt < 4; nt++) {
        int col = wn * 32 + nt * 8 + tig * 2;
        float bb0 = bias[col], bb1 = bias[col + 1];
        #pragma unroll
        for (int mt = 0; mt < 2; mt++) {
            int row = base + wm * 32 + mt * 16 + gid;
            #pragma unroll
            for (int half_row = 0; half_row < 2; half_row++) {
                int r = row + half_row * 8;
                if (r >= N_NODES) continue;
                float vx = fmaxf(acc[mt][nt][half_row * 2 + 0] + bb0, 0.0f);
                float vy = fmaxf(acc[mt][nt][half_row * 2 + 1] + bb1, 0.0f);
                if (HALF_OUT) {
                    __half* ho = (__half*)hout_v;
                    __half2 hv = __floats2half2_rn(vx, vy);
                    *(__half2*)&ho[(size_t)r * CH + col] = hv;
                } else {
                    float* fo = (float*)hout_v;
                    float2 fv = make_float2(vx, vy);
                    *(float2*)&fo[(size_t)r * CH + col] = fv;
                }
            }
        }
    }
}

// ---------------- launch ----------------
extern "C" void kernel_launch(void* const* d_in, const int* in_sizes, int n_in,
                              void* d_out, int out_size) {
    const float* x   = (const float*)d_in[0];
    const int*   ei  = (const int*)d_in[1];      // [2, E]
    const float* W1l = (const float*)d_in[2];
    const float* W1r = (const float*)d_in[3];
    const float* b1  = (const float*)d_in[4];
    const float* W2l = (const float*)d_in[5];
    const float* W2r = (const float*)d_in[6];
    const float* b2  = (const float*)d_in[7];
    const float* W3l = (const float*)d_in[8];
    const float* W3r = (const float*)d_in[9];
    const float* b3  = (const float*)d_in[10];
    float* out = (float*)d_out;

    const int* src = ei;
    const int* dst = ei + N_EDGES;

    __half* h1; __half* h2; __half* Wt2; __half* Wt3; int* zp;
    cudaGetSymbolAddress((void**)&h1, g_h1);
    cudaGetSymbolAddress((void**)&h2, g_h2);
    cudaGetSymbolAddress((void**)&Wt2, g_Wt2);
    cudaGetSymbolAddress((void**)&Wt3, g_Wt3);
    cudaGetSymbolAddress((void**)&zp, g_zeroed);

    // one memset covers deg histogram + lookback flags + fp32 agg accumulators
    cudaMemsetAsync(zp, 0, ZCOUNT * sizeof(int));
    histprep_kernel<<<PREP_BLOCKS + XPAD_BLOCKS + (N_EDGES + 255) / 256, 256>>>(
        src, dst, x, W2l, W2r, W3l, W3r);
    // layer1 depends only on histprep (deg + agg) — runs before scan/fill
    layer1_kernel<<<(N_NODES + 127) / 128, 256>>>(W1l, W1r, b1, h1);
    scanlb_kernel<<<NCHUNK, 1024>>>();
    fill_kernel<<<(N_EDGES + 255) / 256, 256>>>(src, dst);

    layerTC_kernel<true><<<NBLK, 256>>>(h1, (void*)h2, Wt2, b2);
    layerTC_kernel<false><<<NBLK, 256>>>(h2, (void*)out, Wt3, b3);
}

// round 17
// speedup vs baseline: 1.0290x; 1.0290x over previous
#include <cuda_runtime.h>
#include <cuda_fp16.h>
#include <cstdint>

#define N_NODES 100000
#define N_EDGES 600000
#define CH 128
#define NPB 64            // nodes per block tile (tail block handles 32)
#define NBLK 1563         // ceil(100000/64)
#define NCHUNK 98         // ceil(100000/1024)
#define AS_H2 68          // half2 per row: 64 + 4 pad -> conflict-free fragment LDS
#define PREP_BLOCKS 16    // 4096 uint4 / 256
#define XPAD_BLOCKS 391   // ceil(100000/256)
#define EDGE_QUADS 150000 // 600000 / 4
#define EDGE_BLOCKS 586   // ceil(150000/256)
#define ZCOUNT (N_NODES + 2 * NCHUNK)   // deg + lookback words, one memset

// ---------------- scratch (static device globals; no allocation) ----------------
__device__ __align__(16) int g_zeroed[ZCOUNT];   // [0,N): deg; [N,...): lookback u64
__device__ float  g_deginv[N_NODES];
__device__ int    g_off[N_NODES + 1];
__device__ int    g_cur[N_NODES];
__device__ int    g_col[N_EDGES];
__device__ __align__(16) float4 g_x4[N_NODES];   // x padded to 16B rows
__device__ __align__(16) __half g_h1[(size_t)N_NODES * CH];
__device__ __align__(16) __half g_h2[(size_t)N_NODES * CH];
// fp16 fragment-ordered weights: uint4 idx = ((((wn*2+pass)*8 + kt)*2 + g)*32 + lane)
__device__ __align__(16) __half g_Wt2[128 * 256];
__device__ __align__(16) __half g_Wt3[128 * 256];

// ---------------- helpers ----------------
__device__ __forceinline__ int warp_incl_scan(int v, int lane) {
    #pragma unroll
    for (int o = 1; o < 32; o <<= 1) {
        int t = __shfl_up_sync(0xffffffffu, v, o);
        if (lane >= o) v += t;
    }
    return v;
}
__device__ __forceinline__ void mma_f16(float* c, const unsigned* a, const unsigned* b) {
    asm volatile(
        "mma.sync.aligned.m16n8k16.row.col.f32.f16.f16.f32 "
        "{%0,%1,%2,%3}, {%4,%5,%6,%7}, {%8,%9}, {%0,%1,%2,%3};"
        : "+f"(c[0]), "+f"(c[1]), "+f"(c[2]), "+f"(c[3])
        : "r"(a[0]), "r"(a[1]), "r"(a[2]), "r"(a[3]), "r"(b[0]), "r"(b[1]));
}
__device__ __forceinline__ unsigned h2u(__half2 h) {
    return *reinterpret_cast<unsigned*>(&h);
}
__device__ __forceinline__ void acc4_h2(float4& A, uint2 v) {
    float2 lo = __half22float2(*reinterpret_cast<__half2*>(&v.x));
    float2 hi = __half22float2(*reinterpret_cast<__half2*>(&v.y));
    A.x += lo.x; A.y += lo.y; A.z += hi.x; A.w += hi.y;
}

// ---------------- fused prep (16) + x-pad (391) + degree histogram (rest) ----------------
__global__ void histprep_kernel(const int* __restrict__ dst,
                                const float* __restrict__ x,
                                const float* __restrict__ W2l, const float* __restrict__ W2r,
                                const float* __restrict__ W3l, const float* __restrict__ W3r) {
    if (blockIdx.x < PREP_BLOCKS) {
        int p = blockIdx.x * blockDim.x + threadIdx.x;   // 4096 uint4
        if (p >= 4096) return;
        int lane = p & 31;
        int g    = (p >> 5) & 1;
        int kt   = (p >> 6) & 7;
        int pass = (p >> 9) & 1;
        int wn   = (p >> 10) & 3;
        int gid = lane >> 2, tig = lane & 3;
        int k0 = kt * 16 + tig * 2;

        const float* Wa2 = pass ? W2r : W2l;
        const float* Wa3 = pass ? W3r : W3l;

        unsigned out2[4], out3[4];
        #pragma unroll
        for (int j = 0; j < 2; j++) {
            int n = wn * 32 + (g * 2 + j) * 8 + gid;
            out2[j * 2 + 0] = h2u(__floats2half2_rn(Wa2[(k0 + 0) * CH + n], Wa2[(k0 + 1) * CH + n]));
            out2[j * 2 + 1] = h2u(__floats2half2_rn(Wa2[(k0 + 8) * CH + n], Wa2[(k0 + 9) * CH + n]));
            out3[j * 2 + 0] = h2u(__floats2half2_rn(Wa3[(k0 + 0) * CH + n], Wa3[(k0 + 1) * CH + n]));
            out3[j * 2 + 1] = h2u(__floats2half2_rn(Wa3[(k0 + 8) * CH + n], Wa3[(k0 + 9) * CH + n]));
        }
        ((uint4*)g_Wt2)[p] = make_uint4(out2[0], out2[1], out2[2], out2[3]);
        ((uint4*)g_Wt3)[p] = make_uint4(out3[0], out3[1], out3[2], out3[3]);
    } else if (blockIdx.x < PREP_BLOCKS + XPAD_BLOCKS) {
        int i = (blockIdx.x - PREP_BLOCKS) * blockDim.x + threadIdx.x;
        if (i < N_NODES)
            g_x4[i] = make_float4(x[i * 3 + 0], x[i * 3 + 1], x[i * 3 + 2], 0.0f);
    } else {
        // 4 edges/thread, int4 loads, 4 independent atomic chains in flight
        int t = (blockIdx.x - PREP_BLOCKS - XPAD_BLOCKS) * blockDim.x + threadIdx.x;
        if (t < EDGE_QUADS) {
            int4 d4 = ((const int4*)dst)[t];
            atomicAdd(&g_zeroed[d4.x], 1);
            atomicAdd(&g_zeroed[d4.y], 1);
            atomicAdd(&g_zeroed[d4.z], 1);
            atomicAdd(&g_zeroed[d4.w], 1);
        }
    }
}

// ---------------- single-pass decoupled-lookback scan ----------------
__global__ void __launch_bounds__(1024, 1)
scanlb_kernel() {
    __shared__ int wsum[32];
    __shared__ int sh_excl;
    volatile unsigned long long* look =
        (volatile unsigned long long*)(g_zeroed + N_NODES);

    int b = blockIdx.x, tid = threadIdx.x;
    int wid = tid >> 5, lane = tid & 31;
    int i = b * 1024 + tid;
    int v = (i < N_NODES) ? g_zeroed[i] : 0;

    int incl = warp_incl_scan(v, lane);
    if (lane == 31) wsum[wid] = incl;
    __syncthreads();

    if (wid == 0) {
        int ws = wsum[lane];
        int wi = warp_incl_scan(ws, lane);
        wsum[lane] = wi - ws;                     // exclusive warp prefix
        int tot = __shfl_sync(0xffffffffu, wi, 31);

        if (lane == 0)
            look[b] = ((unsigned long long)(b == 0 ? 2u : 1u) << 32) | (unsigned)tot;

        int excl = 0;
        if (b > 0) {
            int win = b - 1;
            while (true) {
                int j = win - lane;
                unsigned long long s = 0;
                if (j >= 0) {
                    do { s = look[j]; } while ((unsigned)(s >> 32) == 0u);
                }
                unsigned flag = (j >= 0) ? (unsigned)(s >> 32) : 0u;
                int val = (int)(unsigned)s;
                unsigned mask = __ballot_sync(0xffffffffu, flag == 2u);
                int contrib;
                if (mask) {
                    int lz = __ffs(mask) - 1;
                    contrib = (lane <= lz && j >= 0) ? val : 0;
                } else {
                    contrib = (j >= 0) ? val : 0;
                }
                #pragma unroll
                for (int o = 16; o > 0; o >>= 1)
                    contrib += __shfl_xor_sync(0xffffffffu, contrib, o);
                excl += contrib;
                if (mask) break;
                win -= 32;
            }
            if (lane == 0)
                look[b] = (2ULL << 32) | (unsigned)(excl + tot);
        }
        if (lane == 0) sh_excl = excl;
    }
    __syncthreads();

    int inclusive = sh_excl + wsum[wid] + incl;
    if (i < N_NODES) {
        g_off[i + 1]  = inclusive;
        g_cur[i]      = inclusive - v;
        g_deginv[i]   = (v > 0) ? (1.0f / (float)v) : 0.0f;
        if (i == 0) g_off[0] = 0;
    }
}

// 4 edges/thread, int4 loads, 4 independent atomic->scatter chains in flight
__global__ void fill_kernel(const int* __restrict__ src, const int* __restrict__ dst) {
    int t = blockIdx.x * blockDim.x + threadIdx.x;
    if (t < EDGE_QUADS) {
        int4 s4 = ((const int4*)src)[t];
        int4 d4 = ((const int4*)dst)[t];
        int p0 = atomicAdd(&g_cur[d4.x], 1);
        int p1 = atomicAdd(&g_cur[d4.y], 1);
        int p2 = atomicAdd(&g_cur[d4.z], 1);
        int p3 = atomicAdd(&g_cur[d4.w], 1);
        g_col[p0] = s4.x;
        g_col[p1] = s4.y;
        g_col[p2] = s4.z;
        g_col[p3] = s4.w;
    }
}

// ---------------- layer 1 (K = 3, fp32 math, fp16 output) ----------------
// Interleaved node-pair gather: each 4-lane subgroup handles nodes nA and nA+32
// concurrently (4 clamped loads in flight per wave, no serial pass boundary).
__global__ void layer1_kernel(const float* __restrict__ Wl,
                              const float* __restrict__ Wr,
                              const float* __restrict__ b,
                              __half* __restrict__ hout) {
    __shared__ __align__(16) float aggx[64][4];
    __shared__ __align__(16) float xs[64][4];
    int tid  = threadIdx.x;
    int warp = tid >> 5, lane = tid & 31;
    int sub  = lane >> 2, sl = lane & 3;        // 8 sub-groups of 4 lanes
    int base = blockIdx.x * 64;

    int nA = warp * 8 + sub;                    // 0..31
    int nB = nA + 32;                           // 32..63
    int nodeA = base + nA, nodeB = base + nB;
    bool okA = nodeA < N_NODES, okB = nodeB < N_NODES;
    int sA = okA ? g_off[nodeA] : 0, eA = okA ? g_off[nodeA + 1] : 0;
    int sB = okB ? g_off[nodeB] : 0, eB = okB ? g_off[nodeB + 1] : 0;
    int safeA = min(sA, N_EDGES - 1);
    int safeB = min(sB, N_EDGES - 1);
    int maxd = max(eA - sA, eB - sB);

    float a0 = 0.f, a1 = 0.f, a2 = 0.f;
    float c0 = 0.f, c1 = 0.f, c2 = 0.f;
    float b0 = 0.f, b1 = 0.f, b2 = 0.f;
    float d0 = 0.f, d1 = 0.f, d2 = 0.f;
    for (int w = 0; w < maxd; w += 8) {
        int iA0 = sA + w + sl, iA1 = iA0 + 4;
        int iB0 = sB + w + sl, iB1 = iB0 + 4;
        bool pA0 = iA0 < eA, pA1 = iA1 < eA;
        bool pB0 = iB0 < eB, pB1 = iB1 < eB;
        int jA0 = g_col[pA0 ? iA0 : safeA];
        int jA1 = g_col[pA1 ? iA1 : safeA];
        int jB0 = g_col[pB0 ? iB0 : safeB];
        int jB1 = g_col[pB1 ? iB1 : safeB];
        float4 vA0 = g_x4[jA0];
        float4 vA1 = g_x4[jA1];
        float4 vB0 = g_x4[jB0];
        float4 vB1 = g_x4[jB1];
        if (pA0) { a0 += vA0.x; a1 += vA0.y; a2 += vA0.z; }
        if (pA1) { c0 += vA1.x; c1 += vA1.y; c2 += vA1.z; }
        if (pB0) { b0 += vB0.x; b1 += vB0.y; b2 += vB0.z; }
        if (pB1) { d0 += vB1.x; d1 += vB1.y; d2 += vB1.z; }
    }
    a0 += c0; a1 += c1; a2 += c2;
    b0 += d0; b1 += d1; b2 += d2;
    #pragma unroll
    for (int o = 1; o < 4; o <<= 1) {
        a0 += __shfl_xor_sync(0xffffffffu, a0, o);
        a1 += __shfl_xor_sync(0xffffffffu, a1, o);
        a2 += __shfl_xor_sync(0xffffffffu, a2, o);
        b0 += __shfl_xor_sync(0xffffffffu, b0, o);
        b1 += __shfl_xor_sync(0xffffffffu, b1, o);
        b2 += __shfl_xor_sync(0xffffffffu, b2, o);
    }
    if (sl == 0) {
        if (okA) {
            float di = g_deginv[nodeA];
            *(float4*)&aggx[nA][0] = make_float4(a0 * di, a1 * di, a2 * di, 0.0f);
            *(float4*)&xs[nA][0] = g_x4[nodeA];
        }
        if (okB) {
            float di = g_deginv[nodeB];
            *(float4*)&aggx[nB][0] = make_float4(b0 * di, b1 * di, b2 * di, 0.0f);
            *(float4*)&xs[nB][0] = g_x4[nodeB];
        }
    }
    __syncthreads();

    // epilogue: col pair = tid&63, node half = tid>>6 (32 nodes each)
    int c2i = tid & 63;
    int g2  = tid >> 6;
    int col = c2i * 2;
    float wl0a = Wl[0 * CH + col],     wl1a = Wl[1 * CH + col],     wl2a = Wl[2 * CH + col];
    float wl0b = Wl[0 * CH + col + 1], wl1b = Wl[1 * CH + col + 1], wl2b = Wl[2 * CH + col + 1];
    float wr0a = Wr[0 * CH + col],     wr1a = Wr[1 * CH + col],     wr2a = Wr[2 * CH + col];
    float wr0b = Wr[0 * CH + col + 1], wr1b = Wr[1 * CH + col + 1], wr2b = Wr[2 * CH + col + 1];
    float bb0 = b[col], bb1 = b[col + 1];

    int nend = min(g2 * 32 + 32, N_NODES - base);
    for (int n = g2 * 32; n < nend; n++) {
        float4 ag = *(const float4*)&aggx[n][0];
        float4 ow = *(const float4*)&xs[n][0];
        float acc0 = bb0 + ag.x * wl0a + ag.y * wl1a + ag.z * wl2a
                         + ow.x * wr0a + ow.y * wr1a + ow.z * wr2a;
        float acc1 = bb1 + ag.x * wl0b + ag.y * wl1b + ag.z * wl2b
                         + ow.x * wr0b + ow.y * wr1b + ow.z * wr2b;
        __half2 hv = __floats2half2_rn(fmaxf(acc0, 0.0f), fmaxf(acc1, 0.0f));
        *(__half2*)&hout[(size_t)(base + n) * CH + col] = hv;
    }
}

// ---------------- layers 2/3: dual-buffer single-sync fp16 TC GEMM ----------------
template <bool HALF_OUT>
__global__ void __launch_bounds__(256, 4)
layerTC_kernel(const __half* __restrict__ hin, void* __restrict__ hout_v,
               const __half* __restrict__ Wt, const float* __restrict__ bias) {
    __shared__ __align__(16) unsigned As[2][NPB * AS_H2];   // 34.8 KB

    int tid  = threadIdx.x;
    int warp = tid >> 5, lane = tid & 31;
    int base = blockIdx.x * NPB;

    int wm = warp >> 2;          // 0..1  -> M rows [wm*32, wm*32+32)
    int wn = warp & 3;           // 0..3  -> N cols [wn*32, wn*32+32)
    int gid = lane >> 2, tig = lane & 3;

    float acc[2][4][4];
    #pragma unroll
    for (int mt = 0; mt < 2; mt++)
        #pragma unroll
        for (int nt = 0; nt < 4; nt++)
            #pragma unroll
            for (int r = 0; r < 4; r++) acc[mt][nt][r] = 0.0f;

    const uint4* Wf = (const uint4*)Wt;

    // ---- Phase A: gather into As[0]; own rows into As[1]; one sync ----
    #pragma unroll
    for (int q = 0; q < 4; q++) {
        int nA = warp + q * 16;
        int nB = nA + 8;
        int nodeA = base + nA, nodeB = base + nB;
        bool okA = nodeA < N_NODES, okB = nodeB < N_NODES;
        int sA = okA ? g_off[nodeA] : 0, eA = okA ? g_off[nodeA + 1] : 0;
        int sB = okB ? g_off[nodeB] : 0, eB = okB ? g_off[nodeB + 1] : 0;
        int safeA = min(sA, N_EDGES - 1);
        int safeB = min(sB, N_EDGES - 1);
        int maxd = max(eA - sA, eB - sB);

        float4 A0 = make_float4(0.f, 0.f, 0.f, 0.f);
        float4 A1 = A0, B0 = A0, B1 = A0;

        for (int w = 0; w < maxd; w += 4) {
            int ja[4], jb[4];
            bool pa[4], pb[4];
            #pragma unroll
            for (int j = 0; j < 4; j++) {
                int ia = sA + w + j, ib = sB + w + j;
                pa[j] = ia < eA;  pb[j] = ib < eB;
                ja[j] = g_col[pa[j] ? ia : safeA];
                jb[j] = g_col[pb[j] ? ib : safeB];
            }
            uint2 va0 = *(const uint2*)&hin[(size_t)ja[0] * CH + lane * 4];
            uint2 va1 = *(const uint2*)&hin[(size_t)ja[1] * CH + lane * 4];
            uint2 va2 = *(const uint2*)&hin[(size_t)ja[2] * CH + lane * 4];
            uint2 va3 = *(const uint2*)&hin[(size_t)ja[3] * CH + lane * 4];
            uint2 vb0 = *(const uint2*)&hin[(size_t)jb[0] * CH + lane * 4];
            uint2 vb1 = *(const uint2*)&hin[(size_t)jb[1] * CH + lane * 4];
            uint2 vb2 = *(const uint2*)&hin[(size_t)jb[2] * CH + lane * 4];
            uint2 vb3 = *(const uint2*)&hin[(size_t)jb[3] * CH + lane * 4];
            if (pa[0]) acc4_h2(A0, va0);
            if (pa[1]) acc4_h2(A1, va1);
            if (pa[2]) acc4_h2(A0, va2);
            if (pa[3]) acc4_h2(A1, va3);
            if (pb[0]) acc4_h2(B0, vb0);
            if (pb[1]) acc4_h2(B1, vb1);
            if (pb[2]) acc4_h2(B0, vb2);
            if (pb[3]) acc4_h2(B1, vb3);
        }

        if (okA) {
            float di = g_deginv[nodeA];
            uint2 st;
            st.x = h2u(__floats2half2_rn((A0.x + A1.x) * di, (A0.y + A1.y) * di));
            st.y = h2u(__floats2half2_rn((A0.z + A1.z) * di, (A0.w + A1.w) * di));
            *(uint2*)&As[0][nA * AS_H2 + lane * 2] = st;
            uint2 own = *(const uint2*)&hin[(size_t)nodeA * CH + lane * 4];
            *(uint2*)&As[1][nA * AS_H2 + lane * 2] = own;
        }
        if (okB) {
            float di = g_deginv[nodeB];
            uint2 st;
            st.x = h2u(__floats2half2_rn((B0.x + B1.x) * di, (B0.y + B1.y) * di));
            st.y = h2u(__floats2half2_rn((B0.z + B1.z) * di, (B0.w + B1.w) * di));
            *(uint2*)&As[0][nB * AS_H2 + lane * 2] = st;
            uint2 own = *(const uint2*)&hin[(size_t)nodeB * CH + lane * 4];
            *(uint2*)&As[1][nB * AS_H2 + lane * 2] = own;
        }
    }
    __syncthreads();

    // ---- Phase B: both passes back-to-back ----
    #pragma unroll
    for (int pass = 0; pass < 2; pass++) {
        #pragma unroll
        for (int kt = 0; kt < 8; kt++) {
            unsigned i0 = ((((unsigned)(wn * 2 + pass) * 8 + kt) * 2) * 32) + lane;
            uint4 q0 = Wf[i0];        // nt 0,1
            uint4 q1 = Wf[i0 + 32];   // nt 2,3
            unsigned bfr[4][2] = {
                { q0.x, q0.y }, { q0.z, q0.w },
                { q1.x, q1.y }, { q1.z, q1.w } };

            unsigned kc = kt * 8;     // half2 column base within row
            #pragma unroll
            for (int mt = 0; mt < 2; mt++) {
                unsigned r0 = (unsigned)(wm * 32 + mt * 16 + gid) * AS_H2 + kc + tig;
                unsigned a[4];
                a[0] = As[pass][r0];
                a[1] = As[pass][r0 + 8 * AS_H2];
                a[2] = As[pass][r0 + 4];
                a[3] = As[pass][r0 + 8 * AS_H2 + 4];
                #pragma unroll
                for (int nt = 0; nt < 4; nt++)
                    mma_f16(acc[mt][nt], a, bfr[nt]);
            }
        }
    }

    // ---- epilogue: bias + relu + store ----
    #pragma unroll
    for (int nt = 0; nt < 4; nt++) {
        int col = wn * 32 + nt * 8 + tig * 2;
        float bb0 = bias[col], bb1 = bias[col + 1];
        #pragma unroll
        for (int mt = 0; mt < 2; mt++) {
            int row = base + wm * 32 + mt * 16 + gid;
            #pragma unroll
            for (int half_row = 0; half_row < 2; half_row++) {
                int r = row + half_row * 8;
                if (r >= N_NODES) continue;
                float vx = fmaxf(acc[mt][nt][half_row * 2 + 0] + bb0, 0.0f);
                float vy = fmaxf(acc[mt][nt][half_row * 2 + 1] + bb1, 0.0f);
                if (HALF_OUT) {
                    __half* ho = (__half*)hout_v;
                    __half2 hv = __floats2half2_rn(vx, vy);
                    *(__half2*)&ho[(size_t)r * CH + col] = hv;
                } else {
                    float* fo = (float*)hout_v;
                    float2 fv = make_float2(vx, vy);
                    *(float2*)&fo[(size_t)r * CH + col] = fv;
                }
            }
        }
    }
}

// ---------------- launch ----------------
extern "C" void kernel_launch(void* const* d_in, const int* in_sizes, int n_in,
                              void* d_out, int out_size) {
    const float* x   = (const float*)d_in[0];
    const int*   ei  = (const int*)d_in[1];      // [2, E]
    const float* W1l = (const float*)d_in[2];
    const float* W1r = (const float*)d_in[3];
    const float* b1  = (const float*)d_in[4];
    const float* W2l = (const float*)d_in[5];
    const float* W2r = (const float*)d_in[6];
    const float* b2  = (const float*)d_in[7];
    const float* W3l = (const float*)d_in[8];
    const float* W3r = (const float*)d_in[9];
    const float* b3  = (const float*)d_in[10];
    float* out = (float*)d_out;

    const int* src = ei;
    const int* dst = ei + N_EDGES;

    __half* h1; __half* h2; __half* Wt2; __half* Wt3; int* zp;
    cudaGetSymbolAddress((void**)&h1, g_h1);
    cudaGetSymbolAddress((void**)&h2, g_h2);
    cudaGetSymbolAddress((void**)&Wt2, g_Wt2);
    cudaGetSymbolAddress((void**)&Wt3, g_Wt3);
    cudaGetSymbolAddress((void**)&zp, g_zeroed);

    // one memset covers deg histogram + lookback flags
    cudaMemsetAsync(zp, 0, ZCOUNT * sizeof(int));
    histprep_kernel<<<PREP_BLOCKS + XPAD_BLOCKS + EDGE_BLOCKS, 256>>>(
        dst, x, W2l, W2r, W3l, W3r);
    scanlb_kernel<<<NCHUNK, 1024>>>();
    fill_kernel<<<EDGE_BLOCKS, 256>>>(src, dst);

    // layers
    layer1_kernel<<<(N_NODES + 63) / 64, 128>>>(W1l, W1r, b1, h1);
    layerTC_kernel<true><<<NBLK, 256>>>(h1, (void*)h2, Wt2, b2);
    layerTC_kernel<false><<<NBLK, 256>>>(h2, (void*)out, Wt3, b3);
}